// round 9
// baseline (speedup 1.0000x reference)
#include <cuda_runtime.h>
#include <stdint.h>

// Problem constants
#define B_ 32
#define N_ 2048
#define M_ 16
#define K_ 32
#define H_ 2
#define NSPLIT 8
#define GRID_BLOCKS (NSPLIT*B_)            // 256
#define ROWS_PER_CHUNK (N_/NSPLIT)         // 256
#define ROWS_PER_WARP  (ROWS_PER_CHUNK/8)  // 32
#define ROW_STRIDE 36                      // smem floats per row
#define TOT (B_*K_*M_)                     // 16384
#define SCHUNKS 64                         // scan chunks (16 (b,k) rows each)

// Scratch (static device globals: no allocation allowed)
// Transposed partials: g_TpartT[sp][m][R], R = b*32+k  (tail reads coalesced)
__device__ float g_TpartT[NSPLIT*TOT];           // 512 KB
__device__ float g_csum_part[NSPLIT*SCHUNKS*M_]; // 32 KB
__device__ unsigned g_ticket = 0u;

// ---------------- f32x2 packed helpers (sm_100a dual-issue FMA) ----------------
typedef unsigned long long u64p;
__device__ __forceinline__ u64p pack2f(float lo, float hi) {
    u64p r; asm("mov.b64 %0, {%1, %2};" : "=l"(r) : "f"(lo), "f"(hi)); return r;
}
__device__ __forceinline__ void unpack2f(u64p v, float& lo, float& hi) {
    asm("mov.b64 {%0, %1}, %2;" : "=f"(lo), "=f"(hi) : "l"(v));
}
__device__ __forceinline__ u64p fma2f(u64p a, u64p b, u64p c) {
    u64p d; asm("fma.rn.f32x2 %0, %1, %2, %3;" : "=l"(d) : "l"(a), "l"(b), "l"(c)); return d;
}
__device__ __forceinline__ u64p mul2f(u64p a, u64p b) {
    u64p d; asm("mul.rn.f32x2 %0, %1, %2;" : "=l"(d) : "l"(a), "l"(b)); return d;
}
__device__ __forceinline__ u64p add2f(u64p a, u64p b) {
    u64p d; asm("add.rn.f32x2 %0, %1, %2;" : "=l"(d) : "l"(a), "l"(b)); return d;
}

// ---------------------------------------------------------------------------
// XLA's f32 tanh approximation (rational 13/6, clamp +-9, |x|<4e-4 -> x).
// ---------------------------------------------------------------------------
__device__ __forceinline__ float xla_tanhf(float x) {
    const float ax = fabsf(x);
    float xc = fminf(fmaxf(x, -9.0f), 9.0f);
    float x2 = xc * xc;
    float num = fmaf(x2, -2.76076847742355e-16f, 2.00018790482477e-13f);
    num = fmaf(x2, num, -8.60467152213735e-11f);
    num = fmaf(x2, num,  5.12229709037114e-08f);
    num = fmaf(x2, num,  1.48572235717979e-05f);
    num = fmaf(x2, num,  6.37261928875436e-04f);
    num = fmaf(x2, num,  4.89352455891786e-03f);
    num = xc * num;
    float den = fmaf(x2,  1.19825839466702e-06f, 1.18534705686654e-04f);
    den = fmaf(x2, den,   2.26843463243900e-03f);
    den = fmaf(x2, den,   4.89352518554385e-03f);
    float r = __fdiv_rn(num, den);
    return (ax < 0.0004f) ? x : r;
}

// ---------------------------------------------------------------------------
// ONE kernel: main compute + (last-block-done) fused tail.
// ---------------------------------------------------------------------------
__global__ void __launch_bounds__(256, 2)
fused_kernel(const float* __restrict__ dgm,
             const float* __restrict__ theta,
             const float* __restrict__ cw,
             float* __restrict__ out) {
    const int b     = blockIdx.y;
    const int chunk = blockIdx.x;
    const int tid   = threadIdx.x;
    const int warp  = tid >> 5;
    const int lane  = tid & 31;          // == k in main phase

    __shared__ float pool[ROWS_PER_CHUNK * ROW_STRIDE];  // 36 KB
    __shared__ int   s_last;

    // =============== Phase A: main compute ===============
    // staging: 256 rows x 17 floats, coalesced; compute w and y^2
    {
        const float c0 = __ldg(cw + 0);
        const float c1 = __ldg(cw + 1);
        const float* __restrict__ src =
            dgm + ((long)b * N_ + (long)chunk * ROWS_PER_CHUNK) * 17;
#pragma unroll
        for (int it = 0; it < 17; ++it) {
            const int idx = it * 256 + tid;          // 0..4351
            const int n   = idx / 17;
            const int c   = idx - n * 17;
            const float v = __ldg(src + idx);
            float* rp = pool + n * ROW_STRIDE;
            if (c == 0) {
                int h = (int)v;
                h = h < 0 ? 0 : (h > (H_ - 1) ? (H_ - 1) : h);
                rp[0] = (h == 0) ? c0 : c1;
            } else {
                rp[3 + c]  = v;        // y  at [4..19]
                rp[19 + c] = v * v;    // y2 at [20..35]
            }
        }
    }

    // th2 pairs for this lane's k (packed f32x2)
    u64p th2p[8];
#pragma unroll
    for (int i = 0; i < 4; ++i) {
        const ulonglong2 tp = *reinterpret_cast<const ulonglong2*>(theta + lane * 16 + i * 4);
        th2p[2*i + 0] = mul2f(tp.x, tp.x);
        th2p[2*i + 1] = mul2f(tp.y, tp.y);
    }

    u64p accp[8];
#pragma unroll
    for (int i = 0; i < 8; ++i) accp[i] = 0ULL;

    __syncthreads();

    // ---- compute: warp owns rows [warp*32, warp*32+32) ----
    const float* __restrict__ rbase = pool + warp * ROWS_PER_WARP * ROW_STRIDE;
    for (int r = 0; r < ROWS_PER_WARP; ++r) {
        const float* rp = rbase + r * ROW_STRIDE;
        const float w = rp[0];
        const ulonglong2 ya = *reinterpret_cast<const ulonglong2*>(rp + 4);
        const ulonglong2 yb = *reinterpret_cast<const ulonglong2*>(rp + 8);
        const ulonglong2 yc = *reinterpret_cast<const ulonglong2*>(rp + 12);
        const ulonglong2 yd = *reinterpret_cast<const ulonglong2*>(rp + 16);
        const ulonglong2 qa = *reinterpret_cast<const ulonglong2*>(rp + 20);
        const ulonglong2 qb = *reinterpret_cast<const ulonglong2*>(rp + 24);
        const ulonglong2 qc = *reinterpret_cast<const ulonglong2*>(rp + 28);
        const ulonglong2 qd = *reinterpret_cast<const ulonglong2*>(rp + 32);

        // zn2 = sum_m y2_m * th2_m  (packed, 2 chains)
        u64p A  = mul2f(qa.x, th2p[0]);
        A       = fma2f(qa.y, th2p[1], A);
        A       = fma2f(qb.x, th2p[2], A);
        A       = fma2f(qb.y, th2p[3], A);
        u64p Bv = mul2f(qc.x, th2p[4]);
        Bv      = fma2f(qc.y, th2p[5], Bv);
        Bv      = fma2f(qd.x, th2p[6], Bv);
        Bv      = fma2f(qd.y, th2p[7], Bv);
        const u64p C = add2f(A, Bv);
        float ulo, uhi; unpack2f(C, ulo, uhi);
        const float u = ulo + uhi;

        // scale = asinh(sqrt(u))/(2*sqrt(u)); small-u poly else MUFU path
        const float p   = 0.5f + u * (-0.08333333333f + u * 0.0375f);
        const float irs = rsqrtf(u);
        const float s1  = __fsqrt_rn(1.0f + u);
        const float rr  = u * irs;
        const float l   = __logf(rr + s1);
        const float sm  = 0.5f * l * irs;
        const float scale = (u < 0.0025f) ? p : sm;
        const float c = w * scale;

        const u64p cc = pack2f(c, c);
        accp[0] = fma2f(cc, ya.x, accp[0]);
        accp[1] = fma2f(cc, ya.y, accp[1]);
        accp[2] = fma2f(cc, yb.x, accp[2]);
        accp[3] = fma2f(cc, yb.y, accp[3]);
        accp[4] = fma2f(cc, yc.x, accp[4]);
        accp[5] = fma2f(cc, yc.y, accp[5]);
        accp[6] = fma2f(cc, yd.x, accp[6]);
        accp[7] = fma2f(cc, yd.y, accp[7]);
    }

    // ---- epilogue: fold theta, reduce 8 warps, write transposed partials ----
    __syncthreads();                       // staging buffer now reusable
    {
        float acc[M_];
#pragma unroll
        for (int i = 0; i < 8; ++i) unpack2f(accp[i], acc[2*i], acc[2*i+1]);
        float th[M_];
#pragma unroll
        for (int i = 0; i < 4; ++i) {
            float4 t = reinterpret_cast<const float4*>(theta)[lane * 4 + i];
            th[4*i+0] = t.x; th[4*i+1] = t.y; th[4*i+2] = t.z; th[4*i+3] = t.w;
        }
#pragma unroll
        for (int m = 0; m < M_; ++m)
            pool[(warp * K_ + lane) * 17 + m] = acc[m] * th[m];
    }
    __syncthreads();

    float* tsum = pool + 8192;             // [K_][M_] per-(k,m) totals
#pragma unroll
    for (int e = tid; e < K_ * M_; e += 256) {
        const int mm = e >> 5, kk = e & 31;   // e = mm*32 + kk
        float s = 0.0f;
#pragma unroll
        for (int w = 0; w < 8; ++w) s += pool[(w * K_ + kk) * 17 + mm];
        g_TpartT[(long)chunk * TOT + mm * 1024 + b * 32 + kk] = s;
        tsum[kk * M_ + mm] = s;
    }
    __syncthreads();

    // per-scan-chunk partial column sums: halves h=0 (k<16), h=1 (k>=16)
    if (tid < 2 * M_) {
        const int h = tid >> 4, m = tid & 15;
        float s = 0.0f;
#pragma unroll
        for (int k = 0; k < 16; ++k) s += tsum[(h * 16 + k) * M_ + m];
        g_csum_part[(long)chunk * (SCHUNKS * M_) + (b * 2 + h) * M_ + m] = s;
    }

    // ============ last-block detection (no spinning, no deadlock) ============
    __threadfence();
    __syncthreads();
    if (tid == 0) {
        unsigned t = atomicAdd(&g_ticket, 1u);
        int last = (t == GRID_BLOCKS - 1u);
        if (last) atomicExch(&g_ticket, 0u);   // reset for next launch/replay
        s_last = last;
    }
    __syncthreads();
    if (!s_last) return;

    // ===================== Fused tail (single block) =====================
    float* csum = pool;          // [64][16]
    float* pref = pool + 1024;   // [64][16]

    for (int idx = tid; idx < SCHUNKS * M_; idx += 256) {
        float s = 0.0f;
#pragma unroll
        for (int sp = 0; sp < NSPLIT; ++sp)
            s += g_csum_part[(long)sp * (SCHUNKS * M_) + idx];
        csum[idx] = s;
    }
    __syncthreads();
    if (tid < M_) {
        float run = 0.0f;
        for (int j2 = 0; j2 < SCHUNKS; ++j2) {
            pref[j2 * M_ + tid] = run;
            run += csum[j2 * M_ + tid];
        }
    }
    __syncthreads();

    // thread -> (chunk jc, m-quad sub). Streams 16 rows of its 4 m-columns.
    const int jc  = tid >> 2;
    const int sub = tid & 3;
    const int m0  = sub * 4;
    const float4 pr4 = *reinterpret_cast<const float4*>(pref + jc * M_ + m0);

    float Si0 = 0.f, Si1 = 0.f, Si2 = 0.f, Si3 = 0.f;

#pragma unroll
    for (int ib = 0; ib < 4; ++ib) {
        float4 red[4];
#pragma unroll
        for (int j = 0; j < 4; ++j) {
            const float* bp = g_TpartT + (m0 + j) * 1024 + jc * 16 + ib * 4;
            float4 a = *reinterpret_cast<const float4*>(bp);
#pragma unroll
            for (int sp = 1; sp < NSPLIT; ++sp) {
                const float4 t2 = *reinterpret_cast<const float4*>(bp + (long)sp * TOT);
                a.x += t2.x; a.y += t2.y; a.z += t2.z; a.w += t2.w;
            }
            red[j] = a;
        }
#pragma unroll
        for (int r = 0; r < 4; ++r) {
            const float v0 = (r==0)?red[0].x:(r==1)?red[0].y:(r==2)?red[0].z:red[0].w;
            const float v1 = (r==0)?red[1].x:(r==1)?red[1].y:(r==2)?red[1].z:red[1].w;
            const float v2 = (r==0)?red[2].x:(r==1)?red[2].y:(r==2)?red[2].z:red[2].w;
            const float v3 = (r==0)?red[3].x:(r==1)?red[3].y:(r==2)?red[3].z:red[3].w;
            Si0 += v0; Si1 += v1; Si2 += v2; Si3 += v3;
            const float S0 = pr4.x + Si0, S1 = pr4.y + Si1;
            const float S2 = pr4.z + Si2, S3 = pr4.w + Si3;

            float tot = S0*S0 + S1*S1 + S2*S2 + S3*S3;
            tot += __shfl_xor_sync(0xFFFFFFFFu, tot, 1);
            tot += __shfl_xor_sync(0xFFFFFFFFu, tot, 2);

            const float sn = __fsqrt_rn(tot);
            const float t  = xla_tanhf(sn);
            const float ai = __fdiv_rn(t, fmaxf(sn, 1e-7f));
            const float xd0 = ai * S0, xd1 = ai * S1, xd2 = ai * S2, xd3 = ai * S3;

            float q = xd0*xd0 + xd1*xd1 + xd2*xd2 + xd3*xd3;
            q += __shfl_xor_sync(0xFFFFFFFFu, q, 1);
            q += __shfl_xor_sync(0xFFFFFFFFu, q, 2);

            const float bi = __fdiv_rn(2.0f, __fadd_rn(1.0f, -q));
            float4 o;
            o.x = xd0 * bi; o.y = xd1 * bi; o.z = xd2 * bi; o.w = xd3 * bi;
            *reinterpret_cast<float4*>(out + (jc * 16 + ib * 4 + r) * 16 + m0) = o;
        }
    }
}

// ---------------------------------------------------------------------------
extern "C" void kernel_launch(void* const* d_in, const int* in_sizes, int n_in,
                              void* d_out, int out_size) {
    const float* dgm   = nullptr;
    const float* theta = nullptr;
    const float* cw    = nullptr;
    for (int i = 0; i < n_in; ++i) {
        if      (in_sizes[i] == B_ * N_ * 17) dgm   = (const float*)d_in[i];
        else if (in_sizes[i] == K_ * M_)      theta = (const float*)d_in[i];
        else if (in_sizes[i] == H_)           cw    = (const float*)d_in[i];
    }
    fused_kernel<<<dim3(NSPLIT, B_), 256>>>(dgm, theta, cw, (float*)d_out);
}

// round 10
// speedup vs baseline: 1.9768x; 1.9768x over previous
#include <cuda_runtime.h>
#include <stdint.h>

// Problem constants
#define B_ 32
#define N_ 2048
#define M_ 16
#define K_ 32
#define H_ 2
#define NSPLIT 8
#define ROWS_PER_CHUNK (N_/NSPLIT)         // 256
#define ROWS_PER_WARP  (ROWS_PER_CHUNK/8)  // 32
#define ROW_STRIDE 36                      // smem floats per row
#define TOT (B_*K_*M_)                     // 16384
#define SCHUNKS 64                         // scan chunks (16 (b,k) rows each)

// Scratch (static device globals: no allocation allowed)
__device__ float g_Tpart[NSPLIT*TOT];            // 512 KB
__device__ float g_csum_part[NSPLIT*SCHUNKS*M_]; // 32 KB

// ---------------------------------------------------------------------------
// Kernel 1: main compute (round-8 proven) with 2-row software pipelining:
// two independent zn2/MUFU chains in flight per iteration; acc updates stay
// in row order (numerics identical to round 8).
// ---------------------------------------------------------------------------
__global__ void __launch_bounds__(256, 2)
main_kernel(const float* __restrict__ dgm,
            const float* __restrict__ theta,
            const float* __restrict__ cw) {
    const int b     = blockIdx.y;
    const int chunk = blockIdx.x;
    const int tid   = threadIdx.x;
    const int warp  = tid >> 5;
    const int lane  = tid & 31;          // == k

    __shared__ float pool[ROWS_PER_CHUNK * ROW_STRIDE];  // 36 KB

    // ---- staging: 256 rows x 17 floats, coalesced; compute w and y^2 ----
    {
        const float c0 = __ldg(cw + 0);
        const float c1 = __ldg(cw + 1);
        const float* __restrict__ src =
            dgm + ((long)b * N_ + (long)chunk * ROWS_PER_CHUNK) * 17;
#pragma unroll
        for (int it = 0; it < 17; ++it) {
            const int idx = it * 256 + tid;          // 0..4351
            const int n   = idx / 17;
            const int c   = idx - n * 17;
            const float v = __ldg(src + idx);
            float* rp = pool + n * ROW_STRIDE;
            if (c == 0) {
                int h = (int)v;
                h = h < 0 ? 0 : (h > (H_ - 1) ? (H_ - 1) : h);
                rp[0] = (h == 0) ? c0 : c1;
            } else {
                rp[3 + c]  = v;        // y  at [4..19]
                rp[19 + c] = v * v;    // y2 at [20..35]
            }
        }
    }

    float th2[M_];
#pragma unroll
    for (int i = 0; i < 4; ++i) {
        float4 t = reinterpret_cast<const float4*>(theta)[lane * 4 + i];
        th2[4*i+0] = t.x * t.x; th2[4*i+1] = t.y * t.y;
        th2[4*i+2] = t.z * t.z; th2[4*i+3] = t.w * t.w;
    }

    float acc[M_];
#pragma unroll
    for (int m = 0; m < M_; ++m) acc[m] = 0.0f;

    __syncthreads();

    // ---- compute: warp owns rows [warp*32, warp*32+32), 2 rows in flight ----
    const float* __restrict__ rbase = pool + warp * ROWS_PER_WARP * ROW_STRIDE;
    for (int r = 0; r < ROWS_PER_WARP; r += 2) {
        const float* rpA = rbase + r * ROW_STRIDE;
        const float* rpB = rpA + ROW_STRIDE;

        // row A zn2
        const float wA = rpA[0];
        {
        }
        const float4 qA0 = *reinterpret_cast<const float4*>(rpA + 20);
        const float4 qA1 = *reinterpret_cast<const float4*>(rpA + 24);
        const float4 qA2 = *reinterpret_cast<const float4*>(rpA + 28);
        const float4 qA3 = *reinterpret_cast<const float4*>(rpA + 32);
        // row B zn2
        const float wB = rpB[0];
        const float4 qB0 = *reinterpret_cast<const float4*>(rpB + 20);
        const float4 qB1 = *reinterpret_cast<const float4*>(rpB + 24);
        const float4 qB2 = *reinterpret_cast<const float4*>(rpB + 28);
        const float4 qB3 = *reinterpret_cast<const float4*>(rpB + 32);

        float dA0 = fmaf(qA0.x, th2[0],  fmaf(qA0.y, th2[1],  fmaf(qA0.z, th2[2],  qA0.w*th2[3])));
        float dB0 = fmaf(qB0.x, th2[0],  fmaf(qB0.y, th2[1],  fmaf(qB0.z, th2[2],  qB0.w*th2[3])));
        float dA1 = fmaf(qA1.x, th2[4],  fmaf(qA1.y, th2[5],  fmaf(qA1.z, th2[6],  qA1.w*th2[7])));
        float dB1 = fmaf(qB1.x, th2[4],  fmaf(qB1.y, th2[5],  fmaf(qB1.z, th2[6],  qB1.w*th2[7])));
        float dA2 = fmaf(qA2.x, th2[8],  fmaf(qA2.y, th2[9],  fmaf(qA2.z, th2[10], qA2.w*th2[11])));
        float dB2 = fmaf(qB2.x, th2[8],  fmaf(qB2.y, th2[9],  fmaf(qB2.z, th2[10], qB2.w*th2[11])));
        float dA3 = fmaf(qA3.x, th2[12], fmaf(qA3.y, th2[13], fmaf(qA3.z, th2[14], qA3.w*th2[15])));
        float dB3 = fmaf(qB3.x, th2[12], fmaf(qB3.y, th2[13], fmaf(qB3.z, th2[14], qB3.w*th2[15])));
        const float uA = (dA0 + dA1) + (dA2 + dA3);
        const float uB = (dB0 + dB1) + (dB2 + dB3);

        // two independent scale chains (MUFU latencies overlap)
        const float pA   = 0.5f + uA * (-0.08333333333f + uA * 0.0375f);
        const float pB   = 0.5f + uB * (-0.08333333333f + uB * 0.0375f);
        const float irsA = rsqrtf(uA);
        const float irsB = rsqrtf(uB);
        const float s1A  = __fsqrt_rn(1.0f + uA);
        const float s1B  = __fsqrt_rn(1.0f + uB);
        const float rrA  = uA * irsA;
        const float rrB  = uB * irsB;
        const float lA   = __logf(rrA + s1A);
        const float lB   = __logf(rrB + s1B);
        const float smA  = 0.5f * lA * irsA;
        const float smB  = 0.5f * lB * irsB;
        const float scaleA = (uA < 0.0025f) ? pA : smA;
        const float scaleB = (uB < 0.0025f) ? pB : smB;
        const float cA = wA * scaleA;
        const float cB = wB * scaleB;

        // acc updates in row order (identical numerics to round 8)
        const float4 yA0 = *reinterpret_cast<const float4*>(rpA + 4);
        const float4 yA1 = *reinterpret_cast<const float4*>(rpA + 8);
        const float4 yA2 = *reinterpret_cast<const float4*>(rpA + 12);
        const float4 yA3 = *reinterpret_cast<const float4*>(rpA + 16);
        acc[0]  = fmaf(cA, yA0.x, acc[0]);   acc[1]  = fmaf(cA, yA0.y, acc[1]);
        acc[2]  = fmaf(cA, yA0.z, acc[2]);   acc[3]  = fmaf(cA, yA0.w, acc[3]);
        acc[4]  = fmaf(cA, yA1.x, acc[4]);   acc[5]  = fmaf(cA, yA1.y, acc[5]);
        acc[6]  = fmaf(cA, yA1.z, acc[6]);   acc[7]  = fmaf(cA, yA1.w, acc[7]);
        acc[8]  = fmaf(cA, yA2.x, acc[8]);   acc[9]  = fmaf(cA, yA2.y, acc[9]);
        acc[10] = fmaf(cA, yA2.z, acc[10]);  acc[11] = fmaf(cA, yA2.w, acc[11]);
        acc[12] = fmaf(cA, yA3.x, acc[12]);  acc[13] = fmaf(cA, yA3.y, acc[13]);
        acc[14] = fmaf(cA, yA3.z, acc[14]);  acc[15] = fmaf(cA, yA3.w, acc[15]);

        const float4 yB0 = *reinterpret_cast<const float4*>(rpB + 4);
        const float4 yB1 = *reinterpret_cast<const float4*>(rpB + 8);
        const float4 yB2 = *reinterpret_cast<const float4*>(rpB + 12);
        const float4 yB3 = *reinterpret_cast<const float4*>(rpB + 16);
        acc[0]  = fmaf(cB, yB0.x, acc[0]);   acc[1]  = fmaf(cB, yB0.y, acc[1]);
        acc[2]  = fmaf(cB, yB0.z, acc[2]);   acc[3]  = fmaf(cB, yB0.w, acc[3]);
        acc[4]  = fmaf(cB, yB1.x, acc[4]);   acc[5]  = fmaf(cB, yB1.y, acc[5]);
        acc[6]  = fmaf(cB, yB1.z, acc[6]);   acc[7]  = fmaf(cB, yB1.w, acc[7]);
        acc[8]  = fmaf(cB, yB2.x, acc[8]);   acc[9]  = fmaf(cB, yB2.y, acc[9]);
        acc[10] = fmaf(cB, yB2.z, acc[10]);  acc[11] = fmaf(cB, yB2.w, acc[11]);
        acc[12] = fmaf(cB, yB3.x, acc[12]);  acc[13] = fmaf(cB, yB3.y, acc[13]);
        acc[14] = fmaf(cB, yB3.z, acc[14]);  acc[15] = fmaf(cB, yB3.w, acc[15]);
    }

    // ---- epilogue: fold theta, reduce 8 warps, write partial + chunk sums ----
    __syncthreads();                       // staging buffer now reusable
    {
        float th[M_];
#pragma unroll
        for (int i = 0; i < 4; ++i) {
            float4 t = reinterpret_cast<const float4*>(theta)[lane * 4 + i];
            th[4*i+0] = t.x; th[4*i+1] = t.y; th[4*i+2] = t.z; th[4*i+3] = t.w;
        }
#pragma unroll
        for (int m = 0; m < M_; ++m)
            pool[(warp * K_ + lane) * 17 + m] = acc[m] * th[m];
    }
    __syncthreads();

    float* tsum = pool + 8192;             // [K_][M_] per-(k,m) totals
#pragma unroll
    for (int idx = tid; idx < K_ * M_; idx += 256) {
        const int kk = idx >> 4, mm = idx & 15;
        float s = 0.0f;
#pragma unroll
        for (int w = 0; w < 8; ++w) s += pool[(w * K_ + kk) * 17 + mm];
        g_Tpart[(long)chunk * TOT + (long)b * (K_ * M_) + idx] = s;
        tsum[idx] = s;
    }
    __syncthreads();

    // per-scan-chunk partial column sums: halves h=0 (k<16), h=1 (k>=16)
    if (tid < 2 * M_) {
        const int h = tid >> 4, m = tid & 15;
        float s = 0.0f;
#pragma unroll
        for (int k = 0; k < 16; ++k) s += tsum[(h * 16 + k) * M_ + m];
        g_csum_part[(long)chunk * (SCHUNKS * M_) + (b * 2 + h) * M_ + m] = s;
    }
}

// ---------------------------------------------------------------------------
// XLA's f32 tanh approximation (rational 13/6, clamp +-9, |x|<4e-4 -> x).
// Tracks the JAX reference where 1/(1-tanh^2) amplifies ULP noise.
// ---------------------------------------------------------------------------
__device__ __forceinline__ float xla_tanhf(float x) {
    const float ax = fabsf(x);
    float xc = fminf(fmaxf(x, -9.0f), 9.0f);
    float x2 = xc * xc;
    float num = fmaf(x2, -2.76076847742355e-16f, 2.00018790482477e-13f);
    num = fmaf(x2, num, -8.60467152213735e-11f);
    num = fmaf(x2, num,  5.12229709037114e-08f);
    num = fmaf(x2, num,  1.48572235717979e-05f);
    num = fmaf(x2, num,  6.37261928875436e-04f);
    num = fmaf(x2, num,  4.89352455891786e-03f);
    num = xc * num;
    float den = fmaf(x2,  1.19825839466702e-06f, 1.18534705686654e-04f);
    den = fmaf(x2, den,   2.26843463243900e-03f);
    den = fmaf(x2, den,   4.89352518554385e-03f);
    float r = __fdiv_rn(num, den);
    return (ax < 0.0004f) ? x : r;
}

// ---------------------------------------------------------------------------
// Kernel 2: fused tail (round-8 proven). Block j (0..63) owns scan chunk j.
// ---------------------------------------------------------------------------
__global__ void __launch_bounds__(256)
tail_kernel(float* __restrict__ out) {
    const int j   = blockIdx.x;
    const int tid = threadIdx.x;

    __shared__ float red[256];            // reduced T for own 16 rows
    __shared__ float csum[SCHUNKS * M_];  // chunk sums (all 64 chunks)

    // (a) reduce own rows over NSPLIT
    {
        float v = 0.0f;
#pragma unroll
        for (int sp = 0; sp < NSPLIT; ++sp)
            v += g_Tpart[(long)sp * TOT + j * 256 + tid];
        red[tid] = v;
    }

    // (b) stage chunk-sum table, reduced over splits (coalesced)
#pragma unroll
    for (int idx = tid; idx < SCHUNKS * M_; idx += 256) {
        float s = 0.0f;
#pragma unroll
        for (int sp = 0; sp < NSPLIT; ++sp)
            s += g_csum_part[(long)sp * (SCHUNKS * M_) + idx];
        csum[idx] = s;
    }
    __syncthreads();

    // (c) prefixes + exp map
    const int ri = tid >> 4;   // row within chunk, 0..15
    const int m  = tid & 15;

    float pref = 0.0f;
    for (int j2 = 0; j2 < j; ++j2) pref += csum[j2 * M_ + m];

    float intra = 0.0f;
#pragma unroll
    for (int i = 0; i < M_; ++i) if (i <= ri) intra += red[i * M_ + m];

    const float S = pref + intra;

    float tot = __fmul_rn(S, S);
#pragma unroll
    for (int d = 1; d < 16; d <<= 1)
        tot = __fadd_rn(tot, __shfl_xor_sync(0xFFFFFFFFu, tot, d));

    const float sn    = __fsqrt_rn(tot);
    const float t     = xla_tanhf(sn);
    const float denom = fmaxf(sn, 1e-7f);
    const float xd    = __fdiv_rn(__fmul_rn(t, S), denom);

    float q = __fmul_rn(xd, xd);
#pragma unroll
    for (int d = 1; d < 16; d <<= 1)
        q = __fadd_rn(q, __shfl_xor_sync(0xFFFFFFFFu, q, d));

    const float omq = __fadd_rn(1.0f, -q);
    out[j * 256 + tid] = __fdiv_rn(__fmul_rn(2.0f, xd), omq);
}

// ---------------------------------------------------------------------------
extern "C" void kernel_launch(void* const* d_in, const int* in_sizes, int n_in,
                              void* d_out, int out_size) {
    const float* dgm   = nullptr;
    const float* theta = nullptr;
    const float* cw    = nullptr;
    for (int i = 0; i < n_in; ++i) {
        if      (in_sizes[i] == B_ * N_ * 17) dgm   = (const float*)d_in[i];
        else if (in_sizes[i] == K_ * M_)      theta = (const float*)d_in[i];
        else if (in_sizes[i] == H_)           cw    = (const float*)d_in[i];
    }
    main_kernel<<<dim3(NSPLIT, B_), 256>>>(dgm, theta, cw);
    tail_kernel<<<SCHUNKS, 256>>>((float*)d_out);
}